// round 4
// baseline (speedup 1.0000x reference)
#include <cuda_runtime.h>
#include <cuda_bf16.h>
#include <cstdint>

// ---------------------------------------------------------------------------
// MultiHeadSelfAttention: B=2, T=2048, D=1024, H=16, DK=64  (fp32 throughout)
//   1) qkv = x @ W_qkv + b_qkv                  (4096 x 3072 x 1024 SGEMM)
//   2) flash-attention per (b,h), 128-row q tiles, online softmax
//   3) out = att @ W_out + b_out                (4096 x 1024 x 1024 SGEMM)
// Scratch lives in __device__ globals (no allocation anywhere).
// ---------------------------------------------------------------------------

#define B_   2
#define T_   2048
#define D_   1024
#define H_   16
#define DK_  64
#define M_   (B_ * T_)      // 4096
#define D3_  (3 * D_)       // 3072

__device__ __align__(16) float g_qkv[(size_t)B_ * T_ * D3_];  // 50.3 MB
__device__ __align__(16) float g_att[(size_t)B_ * T_ * D_];   // 16.8 MB

// ---------------------------------------------------------------------------
// SGEMM:  C[M,N] = A[M,K] @ B[K,N] + bias[N]
// 128x128 block tile, BK=16, 8x8 microtile, 256 threads.
// As stored transposed [BK][128] (+pad) so both operand reads are LDS.128.
// ---------------------------------------------------------------------------
__global__ __launch_bounds__(256, 2)
void sgemm_bias_kernel(const float* __restrict__ A,
                       const float* __restrict__ Bm,
                       const float* __restrict__ bias,
                       float* __restrict__ C,
                       int Mdim, int Ndim, int Kdim)
{
    __shared__ float As[16][132];   // [k][m], padded: stride 132 (16B-aligned rows)
    __shared__ float Bs[16][128];   // [k][n]

    const int tid = threadIdx.x;
    const int tr  = tid >> 4;       // 0..15  (row group)
    const int tc  = tid & 15;       // 0..15  (col group)
    const int m0  = blockIdx.y * 128;
    const int n0  = blockIdx.x * 128;

    float acc[8][8];
#pragma unroll
    for (int i = 0; i < 8; i++)
#pragma unroll
        for (int j = 0; j < 8; j++) acc[i][j] = 0.f;

    for (int k0 = 0; k0 < Kdim; k0 += 16) {
        // load A tile 128x16 (transposed into As)
#pragma unroll
        for (int t = 0; t < 2; t++) {
            int idx = tid + t * 256;          // 0..511, one float4 each
            int row = idx >> 2;               // 0..127
            int cg  = (idx & 3) * 4;          // 0,4,8,12
            float4 v = *(const float4*)(A + (size_t)(m0 + row) * Kdim + k0 + cg);
            As[cg + 0][row] = v.x;
            As[cg + 1][row] = v.y;
            As[cg + 2][row] = v.z;
            As[cg + 3][row] = v.w;
        }
        // load B tile 16x128
#pragma unroll
        for (int t = 0; t < 2; t++) {
            int idx  = tid + t * 256;
            int krow = idx >> 5;              // 0..15
            int nc   = (idx & 31) * 4;        // 0..124
            *(float4*)&Bs[krow][nc] =
                *(const float4*)(Bm + (size_t)(k0 + krow) * Ndim + n0 + nc);
        }
        __syncthreads();

#pragma unroll 8
        for (int kk = 0; kk < 16; kk++) {
            float a[8], b[8];
            *(float4*)(a)     = *(const float4*)&As[kk][tr * 8];
            *(float4*)(a + 4) = *(const float4*)&As[kk][tr * 8 + 4];
            *(float4*)(b)     = *(const float4*)&Bs[kk][tc * 8];
            *(float4*)(b + 4) = *(const float4*)&Bs[kk][tc * 8 + 4];
#pragma unroll
            for (int i = 0; i < 8; i++)
#pragma unroll
                for (int j = 0; j < 8; j++)
                    acc[i][j] = fmaf(a[i], b[j], acc[i][j]);
        }
        __syncthreads();
    }

    // epilogue: add bias, store
#pragma unroll
    for (int i = 0; i < 8; i++) {
        int row = m0 + tr * 8 + i;
#pragma unroll
        for (int j = 0; j < 8; j += 4) {
            int col = n0 + tc * 8 + j;
            float4 bv = *(const float4*)(bias + col);
            float4 o;
            o.x = acc[i][j + 0] + bv.x;
            o.y = acc[i][j + 1] + bv.y;
            o.z = acc[i][j + 2] + bv.z;
            o.w = acc[i][j + 3] + bv.w;
            *(float4*)(C + (size_t)row * Ndim + col) = o;
        }
    }
}

// ---------------------------------------------------------------------------
// Flash attention.
// Grid: (T/128, B*H). Block: 256 threads. One CTA owns 128 query rows of one
// (b,h) head. Online softmax over 16 KV tiles of 128 rows.
// smem: Q^T [64][128] (scale pre-folded), K^T [64][128], V [128][64],
//       P [128][132]. Total 162 KB -> dynamic smem, 1 CTA/SM.
// Thread map: S tile: (tr,tc) -> rows tr*8+i, cols tc*8+j (8x8)
//             O tile: rows tr*8+i, cols tc*4+j (8x4)
// Row stats reduced across the 16 tc-lanes via shfl_xor (1,2,4,8).
// ---------------------------------------------------------------------------
#define PS_STRIDE 132
#define ATTN_SMEM ((64 * 128 + 64 * 128 + 128 * 64 + 128 * PS_STRIDE) * 4)

__global__ __launch_bounds__(256, 1)
void attn_kernel(const float* __restrict__ qkv, float* __restrict__ att)
{
    extern __shared__ float sm[];
    float* Qs = sm;                       // [64][128]  Q^T * scale
    float* Ks = Qs + 64 * 128;            // [64][128]  K^T
    float* Vs = Ks + 64 * 128;            // [128][64]  V
    float* Ps = Vs + 128 * 64;            // [128][PS_STRIDE]

    const int tid = threadIdx.x;
    const int tr  = tid >> 4;
    const int tc  = tid & 15;

    const int q0 = blockIdx.x * 128;
    const int bh = blockIdx.y;
    const int b  = bh >> 4;
    const int h  = bh & 15;

    const float* base = qkv + (size_t)b * T_ * D3_;
    const int qoff = h * DK_;
    const int koff = D_ + h * DK_;
    const int voff = 2 * D_ + h * DK_;
    const float scale = 0.125f;           // 1/sqrt(64)

    // load Q transposed (scale folded in): Qs[dk][q]
    for (int idx = tid; idx < 128 * 16; idx += 256) {
        int f4  = idx >> 7;               // 0..15
        int tok = idx & 127;              // 0..127  (lane-fast -> conflict-free STS)
        float4 v = *(const float4*)(base + (size_t)(q0 + tok) * D3_ + qoff + f4 * 4);
        Qs[(f4 * 4 + 0) * 128 + tok] = v.x * scale;
        Qs[(f4 * 4 + 1) * 128 + tok] = v.y * scale;
        Qs[(f4 * 4 + 2) * 128 + tok] = v.z * scale;
        Qs[(f4 * 4 + 3) * 128 + tok] = v.w * scale;
    }

    float m[8], l[8], acc[8][4];
#pragma unroll
    for (int i = 0; i < 8; i++) {
        m[i] = -1e30f;
        l[i] = 0.f;
#pragma unroll
        for (int j = 0; j < 4; j++) acc[i][j] = 0.f;
    }

    for (int k0 = 0; k0 < T_; k0 += 128) {
        __syncthreads();  // previous tile's PV / S reads done before overwrite

        // K transposed: Ks[dk][krow]
        for (int idx = tid; idx < 128 * 16; idx += 256) {
            int f4  = idx >> 7;
            int tok = idx & 127;
            float4 v = *(const float4*)(base + (size_t)(k0 + tok) * D3_ + koff + f4 * 4);
            Ks[(f4 * 4 + 0) * 128 + tok] = v.x;
            Ks[(f4 * 4 + 1) * 128 + tok] = v.y;
            Ks[(f4 * 4 + 2) * 128 + tok] = v.z;
            Ks[(f4 * 4 + 3) * 128 + tok] = v.w;
        }
        // V natural: Vs[krow][dk]
        for (int idx = tid; idx < 128 * 16; idx += 256) {
            int tok = idx >> 4;
            int f4  = idx & 15;
            *(float4*)(Vs + tok * 64 + f4 * 4) =
                *(const float4*)(base + (size_t)(k0 + tok) * D3_ + voff + f4 * 4);
        }
        __syncthreads();

        // S = (Q*scale) @ K^T   -- 8x8 per thread over dk=64
        float s[8][8];
#pragma unroll
        for (int i = 0; i < 8; i++)
#pragma unroll
            for (int j = 0; j < 8; j++) s[i][j] = 0.f;

#pragma unroll 8
        for (int kk = 0; kk < 64; kk++) {
            float a[8], bb[8];
            *(float4*)(a)      = *(const float4*)(Qs + kk * 128 + tr * 8);
            *(float4*)(a + 4)  = *(const float4*)(Qs + kk * 128 + tr * 8 + 4);
            *(float4*)(bb)     = *(const float4*)(Ks + kk * 128 + tc * 8);
            *(float4*)(bb + 4) = *(const float4*)(Ks + kk * 128 + tc * 8 + 4);
#pragma unroll
            for (int i = 0; i < 8; i++)
#pragma unroll
                for (int j = 0; j < 8; j++)
                    s[i][j] = fmaf(a[i], bb[j], s[i][j]);
        }

        // online softmax update per row
#pragma unroll
        for (int i = 0; i < 8; i++) {
            float rmax = s[i][0];
#pragma unroll
            for (int j = 1; j < 8; j++) rmax = fmaxf(rmax, s[i][j]);
            rmax = fmaxf(rmax, __shfl_xor_sync(0xffffffffu, rmax, 1));
            rmax = fmaxf(rmax, __shfl_xor_sync(0xffffffffu, rmax, 2));
            rmax = fmaxf(rmax, __shfl_xor_sync(0xffffffffu, rmax, 4));
            rmax = fmaxf(rmax, __shfl_xor_sync(0xffffffffu, rmax, 8));
            float mn    = fmaxf(m[i], rmax);
            float alpha = __expf(m[i] - mn);
            m[i] = mn;
            float rs = 0.f;
#pragma unroll
            for (int j = 0; j < 8; j++) {
                float p = __expf(s[i][j] - mn);
                s[i][j] = p;
                rs += p;
            }
            rs += __shfl_xor_sync(0xffffffffu, rs, 1);
            rs += __shfl_xor_sync(0xffffffffu, rs, 2);
            rs += __shfl_xor_sync(0xffffffffu, rs, 4);
            rs += __shfl_xor_sync(0xffffffffu, rs, 8);
            l[i] = l[i] * alpha + rs;
#pragma unroll
            for (int j = 0; j < 4; j++) acc[i][j] *= alpha;
        }

        // stage P in smem (natural [r][c] layout)
#pragma unroll
        for (int i = 0; i < 8; i++) {
            float* pr = Ps + (size_t)(tr * 8 + i) * PS_STRIDE + tc * 8;
            *(float4*)(pr)     = make_float4(s[i][0], s[i][1], s[i][2], s[i][3]);
            *(float4*)(pr + 4) = make_float4(s[i][4], s[i][5], s[i][6], s[i][7]);
        }
        __syncthreads();

        // O += P @ V   -- 8 rows x 4 cols per thread over 128 kv rows
#pragma unroll 8
        for (int kk = 0; kk < 128; kk++) {
            float4 vv = *(const float4*)(Vs + kk * 64 + tc * 4);
#pragma unroll
            for (int i = 0; i < 8; i++) {
                float p = Ps[(size_t)(tr * 8 + i) * PS_STRIDE + kk];
                acc[i][0] = fmaf(p, vv.x, acc[i][0]);
                acc[i][1] = fmaf(p, vv.y, acc[i][1]);
                acc[i][2] = fmaf(p, vv.z, acc[i][2]);
                acc[i][3] = fmaf(p, vv.w, acc[i][3]);
            }
        }
    }

    // epilogue: normalize, write [B,T,D] with head-concat layout
    float* out = att + (size_t)b * T_ * D_ + (size_t)q0 * D_ + h * DK_;
#pragma unroll
    for (int i = 0; i < 8; i++) {
        float inv = 1.f / l[i];
        float4 o;
        o.x = acc[i][0] * inv;
        o.y = acc[i][1] * inv;
        o.z = acc[i][2] * inv;
        o.w = acc[i][3] * inv;
        *(float4*)(out + (size_t)(tr * 8 + i) * D_ + tc * 4) = o;
    }
}

// ---------------------------------------------------------------------------
extern "C" void kernel_launch(void* const* d_in, const int* in_sizes, int n_in,
                              void* d_out, int out_size)
{
    const float* x     = (const float*)d_in[0];
    const float* Wqkv  = (const float*)d_in[1];
    const float* bqkv  = (const float*)d_in[2];
    const float* Wout  = (const float*)d_in[3];
    const float* bout  = (const float*)d_in[4];
    float*       out   = (float*)d_out;

    float *qkv, *att;
    cudaGetSymbolAddress((void**)&qkv, g_qkv);
    cudaGetSymbolAddress((void**)&att, g_att);

    cudaFuncSetAttribute(attn_kernel,
                         cudaFuncAttributeMaxDynamicSharedMemorySize, ATTN_SMEM);

    dim3 blk(256);

    // 1) qkv = x @ W_qkv + b_qkv
    sgemm_bias_kernel<<<dim3(D3_ / 128, M_ / 128), blk>>>(
        x, Wqkv, bqkv, qkv, M_, D3_, D_);

    // 2) attention
    attn_kernel<<<dim3(T_ / 128, B_ * H_), blk, ATTN_SMEM>>>(qkv, att);

    // 3) out = att @ W_out + b_out
    sgemm_bias_kernel<<<dim3(D_ / 128, M_ / 128), blk>>>(
        att, Wout, bout, out, M_, D_, D_);
}

// round 6
// speedup vs baseline: 1.2972x; 1.2972x over previous
#include <cuda_runtime.h>
#include <cuda_bf16.h>
#include <cstdint>

// ---------------------------------------------------------------------------
// MultiHeadSelfAttention: B=2, T=2048, D=1024, H=16, DK=64
//   1) split/transpose prep: fp32 -> bf16 (hi,lo) pairs
//   2) qkv = x @ W_qkv + b_qkv        -- mma.sync bf16 split-3 (fp32 accum)
//   3) flash-attention (fp32 FFMA)    -- epilogue emits bf16 hi/lo pairs
//   4) out = att @ W_out + b_out      -- mma.sync bf16 split-3
// NOTE: harness emits compute_103 PTX -> tcgen05 is unavailable; HMMA
// (mma.sync, sm_80 baseline feature) is the tensor path that compiles.
// ---------------------------------------------------------------------------

#define B_   2
#define T_   2048
#define D_   1024
#define H_   16
#define DK_  64
#define M_   (B_ * T_)      // 4096
#define D3_  (3 * D_)       // 3072

// scratch (__device__ globals; no allocation anywhere)
__device__ __align__(16) float          g_qkv [(size_t)M_ * D3_];
__device__ __align__(16) __nv_bfloat16  g_xh  [(size_t)M_ * D_];
__device__ __align__(16) __nv_bfloat16  g_xl  [(size_t)M_ * D_];
__device__ __align__(16) __nv_bfloat16  g_wqth[(size_t)D3_ * D_];   // W_qkv^T
__device__ __align__(16) __nv_bfloat16  g_wqtl[(size_t)D3_ * D_];
__device__ __align__(16) __nv_bfloat16  g_woth[(size_t)D_ * D_];    // W_out^T
__device__ __align__(16) __nv_bfloat16  g_wotl[(size_t)D_ * D_];
__device__ __align__(16) __nv_bfloat16  g_ath [(size_t)M_ * D_];    // attn out
__device__ __align__(16) __nv_bfloat16  g_atl [(size_t)M_ * D_];

// ---------------------------------------------------------------------------
// PTX helpers (all baseline compute_103 features)
// ---------------------------------------------------------------------------
__device__ __forceinline__ uint32_t smem_to_u32(const void* p) {
    uint32_t a;
    asm("{ .reg .u64 t; cvta.to.shared.u64 t, %1; cvt.u32.u64 %0, t; }"
        : "=r"(a) : "l"(p));
    return a;
}

#define CP_ASYNC16(sa, ga) \
    asm volatile("cp.async.cg.shared.global [%0], [%1], 16;" :: "r"(sa), "l"(ga))
#define CP_COMMIT() asm volatile("cp.async.commit_group;" ::: "memory")
#define CP_WAIT0()  asm volatile("cp.async.wait_group 0;" ::: "memory")
#define CP_WAIT1()  asm volatile("cp.async.wait_group 1;" ::: "memory")

#define LDMX4(r0, r1, r2, r3, addr) \
    asm volatile("ldmatrix.sync.aligned.m8n8.x4.shared.b16 {%0,%1,%2,%3}, [%4];" \
        : "=r"(r0), "=r"(r1), "=r"(r2), "=r"(r3) : "r"(addr))

#define MMA_BF16(d, a, b0, b1) \
    asm volatile("mma.sync.aligned.m16n8k16.row.col.f32.bf16.bf16.f32 " \
        "{%0,%1,%2,%3}, {%4,%5,%6,%7}, {%8,%9}, {%0,%1,%2,%3};" \
        : "+f"((d)[0]), "+f"((d)[1]), "+f"((d)[2]), "+f"((d)[3]) \
        : "r"((a)[0]), "r"((a)[1]), "r"((a)[2]), "r"((a)[3]), "r"(b0), "r"(b1))

// ---------------------------------------------------------------------------
// prep: fp32 -> bf16 hi/lo split
// ---------------------------------------------------------------------------
__global__ void split_kernel(const float* __restrict__ s,
                             __nv_bfloat16* __restrict__ h,
                             __nv_bfloat16* __restrict__ l, int n4)
{
    int i = blockIdx.x * blockDim.x + threadIdx.x;
    if (i >= n4) return;
    float4 v = ((const float4*)s)[i];
    __nv_bfloat16 h0 = __float2bfloat16(v.x), h1 = __float2bfloat16(v.y);
    __nv_bfloat16 h2 = __float2bfloat16(v.z), h3 = __float2bfloat16(v.w);
    __nv_bfloat162 ha; ha.x = h0; ha.y = h1;
    __nv_bfloat162 hb; hb.x = h2; hb.y = h3;
    ((__nv_bfloat162*)h)[i * 2]     = ha;
    ((__nv_bfloat162*)h)[i * 2 + 1] = hb;
    __nv_bfloat162 la, lb;
    la.x = __float2bfloat16(v.x - __bfloat162float(h0));
    la.y = __float2bfloat16(v.y - __bfloat162float(h1));
    lb.x = __float2bfloat16(v.z - __bfloat162float(h2));
    lb.y = __float2bfloat16(v.w - __bfloat162float(h3));
    ((__nv_bfloat162*)l)[i * 2]     = la;
    ((__nv_bfloat162*)l)[i * 2 + 1] = lb;
}

// prep: W[K][N] fp32 -> W^T[N][K] bf16 hi/lo
__global__ void transpose_split_kernel(const float* __restrict__ W,
                                       __nv_bfloat16* __restrict__ Th,
                                       __nv_bfloat16* __restrict__ Tl,
                                       int K, int N)
{
    __shared__ float t[32][33];
    int tx = threadIdx.x, ty = threadIdx.y;
    int n0 = blockIdx.x * 32, k0 = blockIdx.y * 32;
#pragma unroll
    for (int j = ty; j < 32; j += 8)
        t[j][tx] = W[(size_t)(k0 + j) * N + n0 + tx];
    __syncthreads();
#pragma unroll
    for (int j = ty; j < 32; j += 8) {
        float v = t[tx][j];                    // = W[k0+tx][n0+j]
        __nv_bfloat16 h = __float2bfloat16(v);
        size_t o = (size_t)(n0 + j) * K + k0 + tx;
        Th[o] = h;
        Tl[o] = __float2bfloat16(v - __bfloat162float(h));
    }
}

// ---------------------------------------------------------------------------
// HMMA GEMM:  C[M,N] = (Ah+Al)[M,K] @ ((Bh+Bl)[N,K])^T + bias, fp32 out.
// Split-3: Ah*Bh + Ah*Bl + Al*Bh. 128x128 CTA tile, BK=32, 256 thr (8 warps,
// 2x4 -> warp tile 64x32). cp.async double-buffered smem, 80B row stride
// (conflict-free ldmatrix: bank walk 20*i mod 32).
// ---------------------------------------------------------------------------
#define BK          32
#define TSTRIDE     80                         // bytes per smem row
#define TILE_BYTES  (128 * TSTRIDE)            // 10240
#define BUF_BYTES   (4 * TILE_BYTES)           // Ah,Al,Bh,Bl
#define GEMM_SMEM   (2 * BUF_BYTES)            // 81920

__global__ __launch_bounds__(256)
void mma_gemm_kernel(const __nv_bfloat16* __restrict__ Ah,
                     const __nv_bfloat16* __restrict__ Al,
                     const __nv_bfloat16* __restrict__ Bh,
                     const __nv_bfloat16* __restrict__ Bl,
                     const float* __restrict__ bias,
                     float* __restrict__ C,
                     int Ndim, int Kdim)
{
    extern __shared__ char sm[];
    const uint32_t sbase = smem_to_u32(sm);
    const int tid  = threadIdx.x;
    const int lane = tid & 31;
    const int w    = tid >> 5;
    const int wm   = w >> 2;                   // 0..1
    const int wn   = w & 3;                    // 0..3
    const int m0   = blockIdx.y * 128;
    const int n0   = blockIdx.x * 128;

    const __nv_bfloat16* srcs[4] = {
        Ah + (size_t)m0 * Kdim, Al + (size_t)m0 * Kdim,
        Bh + (size_t)n0 * Kdim, Bl + (size_t)n0 * Kdim };

    // ldmatrix per-lane mapping: row-in-16, col-half
    const int lrow = (lane & 7) + ((lane >> 3) & 1) * 8;
    const uint32_t lmoff = (uint32_t)(lrow * TSTRIDE + (lane >> 4) * 16);

    float acc[4][4][4];
#pragma unroll
    for (int mf = 0; mf < 4; mf++)
#pragma unroll
        for (int nf = 0; nf < 4; nf++)
#pragma unroll
            for (int e = 0; e < 4; e++) acc[mf][nf][e] = 0.f;

    // async-load one K-chunk (4 tiles of 128x32 bf16) into buffer `buf`
    auto load_chunk = [&](int c, int buf) {
        const int k0 = c * BK;
        const uint32_t bb = sbase + buf * BUF_BYTES;
#pragma unroll
        for (int t = 0; t < 4; t++) {
#pragma unroll
            for (int it = 0; it < 2; it++) {
                int idx = tid + it * 256;          // 0..511
                int r = idx >> 2, kb = idx & 3;
                const void* g = srcs[t] + (size_t)r * Kdim + k0 + kb * 8;
                uint32_t s = bb + t * TILE_BYTES + r * TSTRIDE + kb * 16;
                CP_ASYNC16(s, g);
            }
        }
        CP_COMMIT();
    };

    const int nchunks = Kdim / BK;
    load_chunk(0, 0);

    for (int c = 0; c < nchunks; c++) {
        const int buf = c & 1;
        if (c + 1 < nchunks) { load_chunk(c + 1, buf ^ 1); CP_WAIT1(); }
        else                 { CP_WAIT0(); }
        __syncthreads();

        const uint32_t tb = sbase + buf * BUF_BYTES;
#pragma unroll
        for (int s = 0; s < 2; s++) {              // two k16 steps per chunk
            const uint32_t koff = s * 32;
            uint32_t ah[4][4], al[4][4];
#pragma unroll
            for (int mf = 0; mf < 4; mf++) {
                uint32_t ra = tb + (uint32_t)((wm * 64 + mf * 16) * TSTRIDE)
                            + koff + lmoff;
                LDMX4(ah[mf][0], ah[mf][1], ah[mf][2], ah[mf][3], ra);
                LDMX4(al[mf][0], al[mf][1], al[mf][2], al[mf][3],
                      ra + TILE_BYTES);
            }
#pragma unroll
            for (int nh = 0; nh < 2; nh++) {
                uint32_t rb = tb + 2 * TILE_BYTES
                            + (uint32_t)((wn * 32 + nh * 16) * TSTRIDE)
                            + koff + lmoff;
                uint32_t bh[4], bl[4];
                LDMX4(bh[0], bh[1], bh[2], bh[3], rb);
                LDMX4(bl[0], bl[1], bl[2], bl[3], rb + TILE_BYTES);
#pragma unroll
                for (int nf2 = 0; nf2 < 2; nf2++) {
                    const int nf = nh * 2 + nf2;
                    uint32_t h0 = bh[nf2], h1 = bh[nf2 + 2];
                    uint32_t l0 = bl[nf2], l1 = bl[nf2 + 2];
#pragma unroll
                    for (int mf = 0; mf < 4; mf++) {
                        MMA_BF16(acc[mf][nf], ah[mf], h0, h1);
                        MMA_BF16(acc[mf][nf], ah[mf], l0, l1);
                        MMA_BF16(acc[mf][nf], al[mf], h0, h1);
                    }
                }
            }
        }
        __syncthreads();   // done reading buf before it is overwritten
    }

    // epilogue: bias + direct stores (c-frag: rows g,g+8; cols 2t,2t+1)
    const int g  = lane >> 2;
    const int t2 = (lane & 3) * 2;
#pragma unroll
    for (int mf = 0; mf < 4; mf++) {
        const int row = m0 + wm * 64 + mf * 16 + g;
#pragma unroll
        for (int nf = 0; nf < 4; nf++) {
            const int col = n0 + wn * 32 + nf * 8 + t2;
            float b0 = __ldg(bias + col), b1 = __ldg(bias + col + 1);
            float2 v0, v1;
            v0.x = acc[mf][nf][0] + b0; v0.y = acc[mf][nf][1] + b1;
            v1.x = acc[mf][nf][2] + b0; v1.y = acc[mf][nf][3] + b1;
            *(float2*)(C + (size_t)row * Ndim + col)       = v0;
            *(float2*)(C + (size_t)(row + 8) * Ndim + col) = v1;
        }
    }
}

// ---------------------------------------------------------------------------
// Flash attention (fp32 FFMA) — epilogue emits bf16 hi/lo pairs.
// Grid: (T/128, B*H), 256 threads, 162 KB smem, 1 CTA/SM.
// ---------------------------------------------------------------------------
#define PS_STRIDE 132
#define ATTN_SMEM ((64 * 128 + 64 * 128 + 128 * 64 + 128 * PS_STRIDE) * 4)

__global__ __launch_bounds__(256, 1)
void attn_kernel(const float* __restrict__ qkv,
                 __nv_bfloat16* __restrict__ outh,
                 __nv_bfloat16* __restrict__ outl)
{
    extern __shared__ float smf[];
    float* Qs = smf;
    float* Ks = Qs + 64 * 128;
    float* Vs = Ks + 64 * 128;
    float* Ps = Vs + 128 * 64;

    const int tid = threadIdx.x;
    const int tr  = tid >> 4;
    const int tc  = tid & 15;
    const int q0  = blockIdx.x * 128;
    const int bh  = blockIdx.y;
    const int b   = bh >> 4;
    const int h   = bh & 15;

    const float* base = qkv + (size_t)b * T_ * D3_;
    const int qoff = h * DK_;
    const int koff = D_ + h * DK_;
    const int voff = 2 * D_ + h * DK_;
    const float scale = 0.125f;

    for (int idx = tid; idx < 128 * 16; idx += 256) {
        int f4 = idx >> 7, tok = idx & 127;
        float4 v = *(const float4*)(base + (size_t)(q0 + tok) * D3_ + qoff + f4 * 4);
        Qs[(f4 * 4 + 0) * 128 + tok] = v.x * scale;
        Qs[(f4 * 4 + 1) * 128 + tok] = v.y * scale;
        Qs[(f4 * 4 + 2) * 128 + tok] = v.z * scale;
        Qs[(f4 * 4 + 3) * 128 + tok] = v.w * scale;
    }

    float m[8], l[8], acc[8][4];
#pragma unroll
    for (int i = 0; i < 8; i++) {
        m[i] = -1e30f; l[i] = 0.f;
#pragma unroll
        for (int j = 0; j < 4; j++) acc[i][j] = 0.f;
    }

    for (int k0 = 0; k0 < T_; k0 += 128) {
        __syncthreads();
        for (int idx = tid; idx < 128 * 16; idx += 256) {
            int f4 = idx >> 7, tok = idx & 127;
            float4 v = *(const float4*)(base + (size_t)(k0 + tok) * D3_ + koff + f4 * 4);
            Ks[(f4 * 4 + 0) * 128 + tok] = v.x;
            Ks[(f4 * 4 + 1) * 128 + tok] = v.y;
            Ks[(f4 * 4 + 2) * 128 + tok] = v.z;
            Ks[(f4 * 4 + 3) * 128 + tok] = v.w;
        }
        for (int idx = tid; idx < 128 * 16; idx += 256) {
            int tok = idx >> 4, f4 = idx & 15;
            *(float4*)(Vs + tok * 64 + f4 * 4) =
                *(const float4*)(base + (size_t)(k0 + tok) * D3_ + voff + f4 * 4);
        }
        __syncthreads();

        float s[8][8];
#pragma unroll
        for (int i = 0; i < 8; i++)
#pragma unroll
            for (int j = 0; j < 8; j++) s[i][j] = 0.f;

#pragma unroll 8
        for (int kk = 0; kk < 64; kk++) {
            float a[8], bb[8];
            *(float4*)(a)      = *(const float4*)(Qs + kk * 128 + tr * 8);
            *(float4*)(a + 4)  = *(const float4*)(Qs + kk * 128 + tr * 8 + 4);
            *(float4*)(bb)     = *(const float4*)(Ks + kk * 128 + tc * 8);
            *(float4*)(bb + 4) = *(const float4*)(Ks + kk * 128 + tc * 8 + 4);
#pragma unroll
            for (int i = 0; i < 8; i++)
#pragma unroll
                for (int j = 0; j < 8; j++)
                    s[i][j] = fmaf(a[i], bb[j], s[i][j]);
        }

#pragma unroll
        for (int i = 0; i < 8; i++) {
            float rmax = s[i][0];
#pragma unroll
            for (int j = 1; j < 8; j++) rmax = fmaxf(rmax, s[i][j]);
            rmax = fmaxf(rmax, __shfl_xor_sync(0xffffffffu, rmax, 1));
            rmax = fmaxf(rmax, __shfl_xor_sync(0xffffffffu, rmax, 2));
            rmax = fmaxf(rmax, __shfl_xor_sync(0xffffffffu, rmax, 4));
            rmax = fmaxf(rmax, __shfl_xor_sync(0xffffffffu, rmax, 8));
            float mn    = fmaxf(m[i], rmax);
            float alpha = __expf(m[i] - mn);
            m[i] = mn;
            float rs = 0.f;
#pragma unroll
            for (int j = 0; j < 8; j++) {
                float p = __expf(s[i][j] - mn);
                s[i][j] = p; rs += p;
            }
            rs += __shfl_xor_sync(0xffffffffu, rs, 1);
            rs += __shfl_xor_sync(0xffffffffu, rs, 2);
            rs += __shfl_xor_sync(0xffffffffu, rs, 4);
            rs += __shfl_xor_sync(0xffffffffu, rs, 8);
            l[i] = l[i] * alpha + rs;
#pragma unroll
            for (int j = 0; j < 4; j++) acc[i][j] *= alpha;
        }

#pragma unroll
        for (int i = 0; i < 8; i++) {
            float* pr = Ps + (size_t)(tr * 8 + i) * PS_STRIDE + tc * 8;
            *(float4*)(pr)     = make_float4(s[i][0], s[i][1], s[i][2], s[i][3]);
            *(float4*)(pr + 4) = make_float4(s[i][4], s[i][5], s[i][6], s[i][7]);
        }
        __syncthreads();

#pragma unroll 8
        for (int kk = 0; kk < 128; kk++) {
            float4 vv = *(const float4*)(Vs + kk * 64 + tc * 4);
#pragma unroll
            for (int i = 0; i < 8; i++) {
                float p = Ps[(size_t)(tr * 8 + i) * PS_STRIDE + kk];
                acc[i][0] = fmaf(p, vv.x, acc[i][0]);
                acc[i][1] = fmaf(p, vv.y, acc[i][1]);
                acc[i][2] = fmaf(p, vv.z, acc[i][2]);
                acc[i][3] = fmaf(p, vv.w, acc[i][3]);
            }
        }
    }

    // epilogue: normalize + bf16 hi/lo split
#pragma unroll
    for (int i = 0; i < 8; i++) {
        float inv = 1.f / l[i];
        float o0 = acc[i][0] * inv, o1 = acc[i][1] * inv;
        float o2 = acc[i][2] * inv, o3 = acc[i][3] * inv;
        __nv_bfloat16 h0 = __float2bfloat16(o0), h1 = __float2bfloat16(o1);
        __nv_bfloat16 h2 = __float2bfloat16(o2), h3 = __float2bfloat16(o3);
        size_t idx = ((size_t)b * T_ + q0 + tr * 8 + i) * D_ + h * DK_ + tc * 4;
        __nv_bfloat162 ph0; ph0.x = h0; ph0.y = h1;
        __nv_bfloat162 ph1; ph1.x = h2; ph1.y = h3;
        *(__nv_bfloat162*)(outh + idx)     = ph0;
        *(__nv_bfloat162*)(outh + idx + 2) = ph1;
        __nv_bfloat162 pl0, pl1;
        pl0.x = __float2bfloat16(o0 - __bfloat162float(h0));
        pl0.y = __float2bfloat16(o1 - __bfloat162float(h1));
        pl1.x = __float2bfloat16(o2 - __bfloat162float(h2));
        pl1.y = __float2bfloat16(o3 - __bfloat162float(h3));
        *(__nv_bfloat162*)(outl + idx)     = pl0;
        *(__nv_bfloat162*)(outl + idx + 2) = pl1;
    }
}

// ---------------------------------------------------------------------------
extern "C" void kernel_launch(void* const* d_in, const int* in_sizes, int n_in,
                              void* d_out, int out_size)
{
    const float* x    = (const float*)d_in[0];
    const float* Wqkv = (const float*)d_in[1];
    const float* bqkv = (const float*)d_in[2];
    const float* Wout = (const float*)d_in[3];
    const float* bout = (const float*)d_in[4];
    float*       out  = (float*)d_out;

    float *qkv;
    __nv_bfloat16 *xh, *xl, *wqth, *wqtl, *woth, *wotl, *ath, *atl;
    cudaGetSymbolAddress((void**)&qkv,  g_qkv);
    cudaGetSymbolAddress((void**)&xh,   g_xh);
    cudaGetSymbolAddress((void**)&xl,   g_xl);
    cudaGetSymbolAddress((void**)&wqth, g_wqth);
    cudaGetSymbolAddress((void**)&wqtl, g_wqtl);
    cudaGetSymbolAddress((void**)&woth, g_woth);
    cudaGetSymbolAddress((void**)&wotl, g_wotl);
    cudaGetSymbolAddress((void**)&ath,  g_ath);
    cudaGetSymbolAddress((void**)&atl,  g_atl);

    cudaFuncSetAttribute(mma_gemm_kernel,
                         cudaFuncAttributeMaxDynamicSharedMemorySize, GEMM_SMEM);
    cudaFuncSetAttribute(attn_kernel,
                         cudaFuncAttributeMaxDynamicSharedMemorySize, ATTN_SMEM);

    // prep
    {
        int n4 = M_ * D_ / 4;
        split_kernel<<<(n4 + 255) / 256, 256>>>(x, xh, xl, n4);
    }
    transpose_split_kernel<<<dim3(D3_ / 32, D_ / 32), dim3(32, 8)>>>(
        Wqkv, wqth, wqtl, D_, D3_);
    transpose_split_kernel<<<dim3(D_ / 32, D_ / 32), dim3(32, 8)>>>(
        Wout, woth, wotl, D_, D_);

    // 1) qkv = x @ W_qkv + b_qkv   (HMMA split-3)
    mma_gemm_kernel<<<dim3(D3_ / 128, M_ / 128), 256, GEMM_SMEM>>>(
        xh, xl, wqth, wqtl, bqkv, qkv, D3_, D_);

    // 2) attention (fp32), emits bf16 pairs
    attn_kernel<<<dim3(T_ / 128, B_ * H_), 256, ATTN_SMEM>>>(qkv, ath, atl);

    // 3) out = att @ W_out + b_out (HMMA split-3)
    mma_gemm_kernel<<<dim3(D_ / 128, M_ / 128), 256, GEMM_SMEM>>>(
        ath, atl, woth, wotl, bout, out, D_, D_);
}

// round 7
// speedup vs baseline: 2.3537x; 1.8144x over previous
#include <cuda_runtime.h>
#include <cuda_bf16.h>
#include <cstdint>

// ---------------------------------------------------------------------------
// MultiHeadSelfAttention: B=2, T=2048, D=1024, H=16, DK=64
//   1) split/transpose prep: fp32 -> bf16 (hi,lo) pairs
//   2) qkv = x @ W_qkv + b_qkv  -- HMMA split-3, epilogue emits bf16 hi/lo
//      (Q columns pre-scaled by 1/8)
//   3) flash-attention           -- HMMA split-3 (QK^T and PV), fp32 softmax
//   4) out = att @ W_out + b_out -- HMMA split-3, fp32 out
// ---------------------------------------------------------------------------

#define B_   2
#define T_   2048
#define D_   1024
#define H_   16
#define DK_  64
#define M_   (B_ * T_)      // 4096
#define D3_  (3 * D_)       // 3072

// scratch (__device__ globals; no allocation anywhere)
__device__ __align__(16) __nv_bfloat16  g_qkvh[(size_t)M_ * D3_];
__device__ __align__(16) __nv_bfloat16  g_qkvl[(size_t)M_ * D3_];
__device__ __align__(16) __nv_bfloat16  g_xh  [(size_t)M_ * D_];
__device__ __align__(16) __nv_bfloat16  g_xl  [(size_t)M_ * D_];
__device__ __align__(16) __nv_bfloat16  g_wqth[(size_t)D3_ * D_];
__device__ __align__(16) __nv_bfloat16  g_wqtl[(size_t)D3_ * D_];
__device__ __align__(16) __nv_bfloat16  g_woth[(size_t)D_ * D_];
__device__ __align__(16) __nv_bfloat16  g_wotl[(size_t)D_ * D_];
__device__ __align__(16) __nv_bfloat16  g_ath [(size_t)M_ * D_];
__device__ __align__(16) __nv_bfloat16  g_atl [(size_t)M_ * D_];

// ---------------------------------------------------------------------------
// PTX helpers (baseline compute_103 features only)
// ---------------------------------------------------------------------------
__device__ __forceinline__ uint32_t smem_to_u32(const void* p) {
    uint32_t a;
    asm("{ .reg .u64 t; cvta.to.shared.u64 t, %1; cvt.u32.u64 %0, t; }"
        : "=r"(a) : "l"(p));
    return a;
}

#define CP_ASYNC16(sa, ga) \
    asm volatile("cp.async.cg.shared.global [%0], [%1], 16;" :: "r"(sa), "l"(ga))
#define CP_COMMIT() asm volatile("cp.async.commit_group;" ::: "memory")
#define CP_WAIT0()  asm volatile("cp.async.wait_group 0;" ::: "memory")
#define CP_WAIT1()  asm volatile("cp.async.wait_group 1;" ::: "memory")

#define LDMX4(r0, r1, r2, r3, addr) \
    asm volatile("ldmatrix.sync.aligned.m8n8.x4.shared.b16 {%0,%1,%2,%3}, [%4];" \
        : "=r"(r0), "=r"(r1), "=r"(r2), "=r"(r3) : "r"(addr))
#define LDMX4T(r0, r1, r2, r3, addr) \
    asm volatile("ldmatrix.sync.aligned.m8n8.x4.trans.shared.b16 {%0,%1,%2,%3}, [%4];" \
        : "=r"(r0), "=r"(r1), "=r"(r2), "=r"(r3) : "r"(addr))

#define MMA_BF16(d, a, b0, b1) \
    asm volatile("mma.sync.aligned.m16n8k16.row.col.f32.bf16.bf16.f32 " \
        "{%0,%1,%2,%3}, {%4,%5,%6,%7}, {%8,%9}, {%0,%1,%2,%3};" \
        : "+f"((d)[0]), "+f"((d)[1]), "+f"((d)[2]), "+f"((d)[3]) \
        : "r"((a)[0]), "r"((a)[1]), "r"((a)[2]), "r"((a)[3]), "r"(b0), "r"(b1))

__device__ __forceinline__ uint32_t pack_bf16(float lo, float hi) {
    __nv_bfloat162 p;
    p.x = __float2bfloat16(lo);
    p.y = __float2bfloat16(hi);
    return *reinterpret_cast<uint32_t*>(&p);
}
// split (x,y) into bf16 hi pair and bf16 residual pair
__device__ __forceinline__ void split2(float x, float y, uint32_t& h, uint32_t& l) {
    __nv_bfloat16 hx = __float2bfloat16(x), hy = __float2bfloat16(y);
    __nv_bfloat162 ph; ph.x = hx; ph.y = hy;
    h = *reinterpret_cast<uint32_t*>(&ph);
    l = pack_bf16(x - __bfloat162float(hx), y - __bfloat162float(hy));
}

// ---------------------------------------------------------------------------
// prep kernels
// ---------------------------------------------------------------------------
__global__ void split_kernel(const float* __restrict__ s,
                             __nv_bfloat16* __restrict__ h,
                             __nv_bfloat16* __restrict__ l, int n4)
{
    int i = blockIdx.x * blockDim.x + threadIdx.x;
    if (i >= n4) return;
    float4 v = ((const float4*)s)[i];
    uint32_t h0, l0, h1, l1;
    split2(v.x, v.y, h0, l0);
    split2(v.z, v.w, h1, l1);
    ((uint32_t*)h)[i * 2]     = h0;
    ((uint32_t*)h)[i * 2 + 1] = h1;
    ((uint32_t*)l)[i * 2]     = l0;
    ((uint32_t*)l)[i * 2 + 1] = l1;
}

__global__ void transpose_split_kernel(const float* __restrict__ W,
                                       __nv_bfloat16* __restrict__ Th,
                                       __nv_bfloat16* __restrict__ Tl,
                                       int K, int N)
{
    __shared__ float t[32][33];
    int tx = threadIdx.x, ty = threadIdx.y;
    int n0 = blockIdx.x * 32, k0 = blockIdx.y * 32;
#pragma unroll
    for (int j = ty; j < 32; j += 8)
        t[j][tx] = W[(size_t)(k0 + j) * N + n0 + tx];
    __syncthreads();
#pragma unroll
    for (int j = ty; j < 32; j += 8) {
        float v = t[tx][j];
        __nv_bfloat16 h = __float2bfloat16(v);
        size_t o = (size_t)(n0 + j) * K + k0 + tx;
        Th[o] = h;
        Tl[o] = __float2bfloat16(v - __bfloat162float(h));
    }
}

// ---------------------------------------------------------------------------
// HMMA GEMM (split-3).  If Ch != nullptr: emit bf16 hi/lo pairs, scaling
// columns < qcols by 0.125 (exact pow2).  Else: fp32 C.
// ---------------------------------------------------------------------------
#define BK          32
#define TSTRIDE     80
#define TILE_BYTES  (128 * TSTRIDE)
#define BUF_BYTES   (4 * TILE_BYTES)
#define GEMM_SMEM   (2 * BUF_BYTES)

__global__ __launch_bounds__(256)
void mma_gemm_kernel(const __nv_bfloat16* __restrict__ Ah,
                     const __nv_bfloat16* __restrict__ Al,
                     const __nv_bfloat16* __restrict__ Bh,
                     const __nv_bfloat16* __restrict__ Bl,
                     const float* __restrict__ bias,
                     float* __restrict__ C,
                     __nv_bfloat16* __restrict__ Ch,
                     __nv_bfloat16* __restrict__ Cl,
                     int qcols, int Ndim, int Kdim)
{
    extern __shared__ char sm[];
    const uint32_t sbase = smem_to_u32(sm);
    const int tid  = threadIdx.x;
    const int lane = tid & 31;
    const int w    = tid >> 5;
    const int wm   = w >> 2;
    const int wn   = w & 3;
    const int m0   = blockIdx.y * 128;
    const int n0   = blockIdx.x * 128;

    const __nv_bfloat16* srcs[4] = {
        Ah + (size_t)m0 * Kdim, Al + (size_t)m0 * Kdim,
        Bh + (size_t)n0 * Kdim, Bl + (size_t)n0 * Kdim };

    const int lrow = (lane & 7) + ((lane >> 3) & 1) * 8;
    const uint32_t lmoff = (uint32_t)(lrow * TSTRIDE + (lane >> 4) * 16);

    float acc[4][4][4];
#pragma unroll
    for (int mf = 0; mf < 4; mf++)
#pragma unroll
        for (int nf = 0; nf < 4; nf++)
#pragma unroll
            for (int e = 0; e < 4; e++) acc[mf][nf][e] = 0.f;

    auto load_chunk = [&](int c, int buf) {
        const int k0 = c * BK;
        const uint32_t bb = sbase + buf * BUF_BYTES;
#pragma unroll
        for (int t = 0; t < 4; t++) {
#pragma unroll
            for (int it = 0; it < 2; it++) {
                int idx = tid + it * 256;
                int r = idx >> 2, kb = idx & 3;
                const void* g = srcs[t] + (size_t)r * Kdim + k0 + kb * 8;
                uint32_t s = bb + t * TILE_BYTES + r * TSTRIDE + kb * 16;
                CP_ASYNC16(s, g);
            }
        }
        CP_COMMIT();
    };

    const int nchunks = Kdim / BK;
    load_chunk(0, 0);

    for (int c = 0; c < nchunks; c++) {
        const int buf = c & 1;
        if (c + 1 < nchunks) { load_chunk(c + 1, buf ^ 1); CP_WAIT1(); }
        else                 { CP_WAIT0(); }
        __syncthreads();

        const uint32_t tb = sbase + buf * BUF_BYTES;
#pragma unroll
        for (int s = 0; s < 2; s++) {
            const uint32_t koff = s * 32;
            uint32_t ah[4][4], al[4][4];
#pragma unroll
            for (int mf = 0; mf < 4; mf++) {
                uint32_t ra = tb + (uint32_t)((wm * 64 + mf * 16) * TSTRIDE)
                            + koff + lmoff;
                LDMX4(ah[mf][0], ah[mf][1], ah[mf][2], ah[mf][3], ra);
                LDMX4(al[mf][0], al[mf][1], al[mf][2], al[mf][3],
                      ra + TILE_BYTES);
            }
#pragma unroll
            for (int nh = 0; nh < 2; nh++) {
                uint32_t rb = tb + 2 * TILE_BYTES
                            + (uint32_t)((wn * 32 + nh * 16) * TSTRIDE)
                            + koff + lmoff;
                uint32_t bh[4], bl[4];
                LDMX4(bh[0], bh[1], bh[2], bh[3], rb);
                LDMX4(bl[0], bl[1], bl[2], bl[3], rb + TILE_BYTES);
#pragma unroll
                for (int nf2 = 0; nf2 < 2; nf2++) {
                    const int nf = nh * 2 + nf2;
                    uint32_t h0 = bh[nf2], h1 = bh[nf2 + 2];
                    uint32_t l0 = bl[nf2], l1 = bl[nf2 + 2];
#pragma unroll
                    for (int mf = 0; mf < 4; mf++) {
                        MMA_BF16(acc[mf][nf], ah[mf], h0, h1);
                        MMA_BF16(acc[mf][nf], ah[mf], l0, l1);
                        MMA_BF16(acc[mf][nf], al[mf], h0, h1);
                    }
                }
            }
        }
        __syncthreads();
    }

    const int g  = lane >> 2;
    const int t2 = (lane & 3) * 2;
#pragma unroll
    for (int mf = 0; mf < 4; mf++) {
        const int row = m0 + wm * 64 + mf * 16 + g;
#pragma unroll
        for (int nf = 0; nf < 4; nf++) {
            const int col = n0 + wn * 32 + nf * 8 + t2;
            float b0 = __ldg(bias + col), b1 = __ldg(bias + col + 1);
            float v00 = acc[mf][nf][0] + b0, v01 = acc[mf][nf][1] + b1;
            float v10 = acc[mf][nf][2] + b0, v11 = acc[mf][nf][3] + b1;
            if (Ch) {
                float sc = (col < qcols) ? 0.125f : 1.0f;
                v00 *= sc; v01 *= sc; v10 *= sc; v11 *= sc;
                uint32_t h0, l0, h1, l1;
                split2(v00, v01, h0, l0);
                split2(v10, v11, h1, l1);
                size_t o0 = (size_t)row * Ndim + col;
                size_t o1 = (size_t)(row + 8) * Ndim + col;
                *(uint32_t*)(Ch + o0) = h0;  *(uint32_t*)(Cl + o0) = l0;
                *(uint32_t*)(Ch + o1) = h1;  *(uint32_t*)(Cl + o1) = l1;
            } else {
                float2 w0, w1;
                w0.x = v00; w0.y = v01;
                w1.x = v10; w1.y = v11;
                *(float2*)(C + (size_t)row * Ndim + col)       = w0;
                *(float2*)(C + (size_t)(row + 8) * Ndim + col) = w1;
            }
        }
    }
}

// ---------------------------------------------------------------------------
// HMMA flash attention (split-3 QK^T and PV).
// Grid (T/128, B*H), 256 thr (8 warps x 16 q-rows). Q frags in registers.
// KV tiles of 64, double-buffered cp.async. smem row stride 144B.
// ---------------------------------------------------------------------------
#define KV      64
#define AST     144                      // bytes per smem row (64 bf16 + pad)
#define TEN_B   (KV * AST)               // 9216 per tensor
#define ABUF    (4 * TEN_B)              // Khi,Klo,Vhi,Vlo = 36864
#define ATTN_SMEM (2 * ABUF)             // 73728

__global__ __launch_bounds__(256, 2)
void attn_mma_kernel(const __nv_bfloat16* __restrict__ qkvh,
                     const __nv_bfloat16* __restrict__ qkvl,
                     __nv_bfloat16* __restrict__ outh,
                     __nv_bfloat16* __restrict__ outl)
{
    extern __shared__ char sm[];
    const uint32_t sb = smem_to_u32(sm);
    const int tid  = threadIdx.x;
    const int lane = tid & 31;
    const int w    = tid >> 5;

    const int q0 = blockIdx.x * 128;
    const int bh = blockIdx.y;
    const int b  = bh >> 4;
    const int h  = bh & 15;

    const __nv_bfloat16* baseh = qkvh + (size_t)b * T_ * D3_;
    const __nv_bfloat16* basel = qkvl + (size_t)b * T_ * D3_;

    const int g  = lane >> 2;
    const int t2 = (lane & 3) * 2;
    const int lrow = (lane & 7) + ((lane >> 3) & 1) * 8;
    const uint32_t lmcol = (uint32_t)((lane >> 4) * 16);
    // trans-ldmatrix lane mapping for V
    const int vtok = (lane & 7) + ((lane >> 4) & 1) * 8;
    const uint32_t vdk16 = (uint32_t)(((lane >> 3) & 1) * 16);

    // ---- stage Q (hi/lo) into buffer 0, build register fragments
#pragma unroll
    for (int i = tid; i < 2048; i += 256) {
        int sp = i >> 10, rem = i & 1023;
        int row = rem >> 3, ch = rem & 7;
        const __nv_bfloat16* src =
            (sp ? basel : baseh) + (size_t)(q0 + row) * D3_ + h * DK_ + ch * 8;
        CP_ASYNC16(sb + sp * (128 * AST) + row * AST + ch * 16, src);
    }
    CP_COMMIT(); CP_WAIT0();
    __syncthreads();

    uint32_t qhf[4][4], qlf[4][4];
#pragma unroll
    for (int kc = 0; kc < 4; kc++) {
        uint32_t ra = sb + (uint32_t)((w * 16 + lrow) * AST) + kc * 32 + lmcol;
        LDMX4(qhf[kc][0], qhf[kc][1], qhf[kc][2], qhf[kc][3], ra);
        LDMX4(qlf[kc][0], qlf[kc][1], qlf[kc][2], qlf[kc][3], ra + 128 * AST);
    }
    __syncthreads();

    // KV tile loader: Khi,Klo,Vhi,Vlo each [64][64] bf16
    auto load_kv = [&](int t, int buf) {
        const int k0 = t * KV;
        const uint32_t bb = sb + buf * ABUF;
        const __nv_bfloat16* srcs[4] = {
            baseh + D_ + h * DK_,  basel + D_ + h * DK_,
            baseh + 2 * D_ + h * DK_, basel + 2 * D_ + h * DK_ };
#pragma unroll
        for (int i = tid; i < 2048; i += 256) {
            int ten = i >> 9, rem = i & 511;
            int row = rem >> 3, ch = rem & 7;
            CP_ASYNC16(bb + ten * TEN_B + row * AST + ch * 16,
                       srcs[ten] + (size_t)(k0 + row) * D3_ + ch * 8);
        }
        CP_COMMIT();
    };

    float m0 = -1e30f, m1 = -1e30f, l0 = 0.f, l1 = 0.f;
    float oacc[8][4];
#pragma unroll
    for (int j = 0; j < 8; j++)
#pragma unroll
        for (int e = 0; e < 4; e++) oacc[j][e] = 0.f;

    const int ntiles = T_ / KV;           // 32
    load_kv(0, 0);

    for (int t = 0; t < ntiles; t++) {
        const int buf = t & 1;
        if (t + 1 < ntiles) { load_kv(t + 1, buf ^ 1); CP_WAIT1(); }
        else                { CP_WAIT0(); }
        __syncthreads();
        const uint32_t kb = sb + buf * ABUF;

        // ---- S = Q K^T  (8 n-tiles of 8 toks)
        float sf[8][4];
#pragma unroll
        for (int nt = 0; nt < 8; nt++)
#pragma unroll
            for (int e = 0; e < 4; e++) sf[nt][e] = 0.f;

#pragma unroll
        for (int p = 0; p < 4; p++) {
#pragma unroll
            for (int kc = 0; kc < 4; kc++) {
                uint32_t rb = kb + (uint32_t)((p * 16 + lrow) * AST)
                            + kc * 32 + lmcol;
                uint32_t kh[4], kl[4];
                LDMX4(kh[0], kh[1], kh[2], kh[3], rb);
                LDMX4(kl[0], kl[1], kl[2], kl[3], rb + TEN_B);
                MMA_BF16(sf[2 * p],     qhf[kc], kh[0], kh[2]);
                MMA_BF16(sf[2 * p],     qhf[kc], kl[0], kl[2]);
                MMA_BF16(sf[2 * p],     qlf[kc], kh[0], kh[2]);
                MMA_BF16(sf[2 * p + 1], qhf[kc], kh[1], kh[3]);
                MMA_BF16(sf[2 * p + 1], qhf[kc], kl[1], kl[3]);
                MMA_BF16(sf[2 * p + 1], qlf[kc], kh[1], kh[3]);
            }
        }

        // ---- online softmax (rows g, g+8; quad shfl reduction)
        float vx0 = -1e30f, vx1 = -1e30f;
#pragma unroll
        for (int nt = 0; nt < 8; nt++) {
            vx0 = fmaxf(vx0, fmaxf(sf[nt][0], sf[nt][1]));
            vx1 = fmaxf(vx1, fmaxf(sf[nt][2], sf[nt][3]));
        }
        vx0 = fmaxf(vx0, __shfl_xor_sync(0xffffffffu, vx0, 1));
        vx0 = fmaxf(vx0, __shfl_xor_sync(0xffffffffu, vx0, 2));
        vx1 = fmaxf(vx1, __shfl_xor_sync(0xffffffffu, vx1, 1));
        vx1 = fmaxf(vx1, __shfl_xor_sync(0xffffffffu, vx1, 2));
        float mn0 = fmaxf(m0, vx0), mn1 = fmaxf(m1, vx1);
        float a0 = __expf(m0 - mn0), a1 = __expf(m1 - mn1);
        m0 = mn0; m1 = mn1;

        float rs0 = 0.f, rs1 = 0.f;
#pragma unroll
        for (int nt = 0; nt < 8; nt++) {
            sf[nt][0] = __expf(sf[nt][0] - mn0);
            sf[nt][1] = __expf(sf[nt][1] - mn0);
            sf[nt][2] = __expf(sf[nt][2] - mn1);
            sf[nt][3] = __expf(sf[nt][3] - mn1);
            rs0 += sf[nt][0] + sf[nt][1];
            rs1 += sf[nt][2] + sf[nt][3];
        }
        rs0 += __shfl_xor_sync(0xffffffffu, rs0, 1);
        rs0 += __shfl_xor_sync(0xffffffffu, rs0, 2);
        rs1 += __shfl_xor_sync(0xffffffffu, rs1, 1);
        rs1 += __shfl_xor_sync(0xffffffffu, rs1, 2);
        l0 = l0 * a0 + rs0;
        l1 = l1 * a1 + rs1;
#pragma unroll
        for (int j = 0; j < 8; j++) {
            oacc[j][0] *= a0; oacc[j][1] *= a0;
            oacc[j][2] *= a1; oacc[j][3] *= a1;
        }

        // ---- O += P V  (P split to bf16 hi/lo in registers)
#pragma unroll
        for (int kf = 0; kf < 4; kf++) {
            uint32_t pah[4], pal[4];
            split2(sf[2 * kf][0],     sf[2 * kf][1],     pah[0], pal[0]);
            split2(sf[2 * kf][2],     sf[2 * kf][3],     pah[1], pal[1]);
            split2(sf[2 * kf + 1][0], sf[2 * kf + 1][1], pah[2], pal[2]);
            split2(sf[2 * kf + 1][2], sf[2 * kf + 1][3], pah[3], pal[3]);
#pragma unroll
            for (int dp = 0; dp < 4; dp++) {
                uint32_t va = kb + 2 * TEN_B
                            + (uint32_t)((kf * 16 + vtok) * AST)
                            + dp * 32 + vdk16;
                uint32_t vh[4], vl[4];
                LDMX4T(vh[0], vh[1], vh[2], vh[3], va);
                LDMX4T(vl[0], vl[1], vl[2], vl[3], va + TEN_B);
                MMA_BF16(oacc[2 * dp],     pah, vh[0], vh[2]);
                MMA_BF16(oacc[2 * dp],     pah, vl[0], vl[2]);
                MMA_BF16(oacc[2 * dp],     pal, vh[0], vh[2]);
                MMA_BF16(oacc[2 * dp + 1], pah, vh[1], vh[3]);
                MMA_BF16(oacc[2 * dp + 1], pah, vl[1], vl[3]);
                MMA_BF16(oacc[2 * dp + 1], pal, vh[1], vh[3]);
            }
        }
        __syncthreads();
    }

    // ---- epilogue: normalize, split to bf16 hi/lo pairs
    const float inv0 = 1.f / l0, inv1 = 1.f / l1;
    const size_t r0 = (size_t)(b * T_ + q0 + w * 16 + g) * D_ + h * DK_;
    const size_t r1 = r0 + 8 * D_;
#pragma unroll
    for (int j = 0; j < 8; j++) {
        uint32_t hh, ll;
        split2(oacc[j][0] * inv0, oacc[j][1] * inv0, hh, ll);
        *(uint32_t*)(outh + r0 + j * 8 + t2) = hh;
        *(uint32_t*)(outl + r0 + j * 8 + t2) = ll;
        split2(oacc[j][2] * inv1, oacc[j][3] * inv1, hh, ll);
        *(uint32_t*)(outh + r1 + j * 8 + t2) = hh;
        *(uint32_t*)(outl + r1 + j * 8 + t2) = ll;
    }
}

// ---------------------------------------------------------------------------
extern "C" void kernel_launch(void* const* d_in, const int* in_sizes, int n_in,
                              void* d_out, int out_size)
{
    const float* x    = (const float*)d_in[0];
    const float* Wqkv = (const float*)d_in[1];
    const float* bqkv = (const float*)d_in[2];
    const float* Wout = (const float*)d_in[3];
    const float* bout = (const float*)d_in[4];
    float*       out  = (float*)d_out;

    __nv_bfloat16 *qkvh, *qkvl, *xh, *xl, *wqth, *wqtl, *woth, *wotl, *ath, *atl;
    cudaGetSymbolAddress((void**)&qkvh, g_qkvh);
    cudaGetSymbolAddress((void**)&qkvl, g_qkvl);
    cudaGetSymbolAddress((void**)&xh,   g_xh);
    cudaGetSymbolAddress((void**)&xl,   g_xl);
    cudaGetSymbolAddress((void**)&wqth, g_wqth);
    cudaGetSymbolAddress((void**)&wqtl, g_wqtl);
    cudaGetSymbolAddress((void**)&woth, g_woth);
    cudaGetSymbolAddress((void**)&wotl, g_wotl);
    cudaGetSymbolAddress((void**)&ath,  g_ath);
    cudaGetSymbolAddress((void**)&atl,  g_atl);

    cudaFuncSetAttribute(mma_gemm_kernel,
                         cudaFuncAttributeMaxDynamicSharedMemorySize, GEMM_SMEM);
    cudaFuncSetAttribute(attn_mma_kernel,
                         cudaFuncAttributeMaxDynamicSharedMemorySize, ATTN_SMEM);

    // prep
    {
        int n4 = M_ * D_ / 4;
        split_kernel<<<(n4 + 255) / 256, 256>>>(x, xh, xl, n4);
    }
    transpose_split_kernel<<<dim3(D3_ / 32, D_ / 32), dim3(32, 8)>>>(
        Wqkv, wqth, wqtl, D_, D3_);
    transpose_split_kernel<<<dim3(D_ / 32, D_ / 32), dim3(32, 8)>>>(
        Wout, woth, wotl, D_, D_);

    // 1) qkv = x @ W_qkv + b_qkv -> bf16 hi/lo, Q cols pre-scaled by 1/8
    mma_gemm_kernel<<<dim3(D3_ / 128, M_ / 128), 256, GEMM_SMEM>>>(
        xh, xl, wqth, wqtl, bqkv, nullptr, qkvh, qkvl, D_, D3_, D_);

    // 2) attention (HMMA split-3), emits bf16 hi/lo pairs
    attn_mma_kernel<<<dim3(T_ / 128, B_ * H_), 256, ATTN_SMEM>>>(
        qkvh, qkvl, ath, atl);

    // 3) out = att @ W_out + b_out (fp32 out)
    mma_gemm_kernel<<<dim3(D_ / 128, M_ / 128), 256, GEMM_SMEM>>>(
        ath, atl, woth, wotl, bout, out, nullptr, nullptr, 0, D_, D_);
}